// round 16
// baseline (speedup 1.0000x reference)
#include <cuda_runtime.h>
#include <math.h>

#define BATCH 128
#define CTX 64
#define HID 128
#define KSLICES 19            // 9 time + 9 dist + 1 hidden
#define KTOT (KSLICES*128)    // 2432
#define KGROUPS 16
#define KG 152                // KTOT / KGROUPS

typedef unsigned long long u64;

// Scratch (__device__ globals: allocation-free rule)
__device__ float g_Xagg[BATCH * KTOT];             // [b][k] row-major
__device__ float g_gpart[KGROUPS * BATCH * HID];   // per-kgroup GEMM partials

// ---- packed f32x2 helpers --------------------------------------------------
__device__ __forceinline__ u64 pack2(float v) {
    u64 r; asm("mov.b64 %0, {%1, %1};" : "=l"(r) : "f"(v)); return r;
}
__device__ __forceinline__ void ffma2(u64& d, u64 a, u64 b) {
    asm("fma.rn.f32x2 %0, %1, %2, %0;" : "+l"(d) : "l"(a), "l"(b));
}
__device__ __forceinline__ u64 fadd2(u64 a, u64 b) {
    u64 r; asm("add.rn.f32x2 %0, %1, %2;" : "=l"(r) : "l"(a), "l"(b)); return r;
}

// ---------------------------------------------------------------------------
// K1: per-batch slot aggregation  acc[18][128] = sel[18][64] @ x[64][128]
//   grid = 128 (batch), 512 threads = 8 ctx-groups x 64 dim-pairs.
//   Warp-local mask-dtype sniff in the 4 sel-writer warps (no prologue syncs).
//   dynamic smem: sel2 9216B + red[8] 73728B = 82944B.  (16.6us-best body)
// ---------------------------------------------------------------------------
#define K1_SMEM (9216 + 73728)
__global__ __launch_bounds__(512, 1)
void k1_aggregate(const float* __restrict__ x,     // [B][CTX][128]
                  const int* __restrict__ timec,   // [B][CTX]
                  const int* __restrict__ distc,   // [B][CTX]
                  const void* __restrict__ maskp,  // [B][CTX] int32 OR bytes
                  const float* __restrict__ h)     // [B][128]
{
    extern __shared__ __align__(16) char smraw[];
    u64*   sel2 = (u64*)smraw;                 // [c][s] : c*18+s
    float* red  = (float*)(smraw + 9216);      // [g][i] : g*2304+i

    const int b   = blockIdx.x;
    const int tid = threadIdx.x;
    const int g   = tid >> 6;   // ctx group: c in [8g, 8g+8)
    const int q   = tid & 63;   // dim pair:  dims 2q, 2q+1

    // ---- front-issue ALL global loads (one latency round trip) ----
    u64 xv[8];
    {
        const float* xb = x + (size_t)b * CTX * 128 + q * 2;
        #pragma unroll
        for (int cc = 0; cc < 8; cc++)
            xv[cc] = *(const u64*)(xb + (g * 8 + cc) * 128);
    }
    float hv = 0.0f;
    if (tid < 128) hv = h[b * HID + tid];

    // sel2 writers (warps 0-3): warp-local dtype sniff + sel2 write
    if (tid < 128) {
        unsigned sniffw = ((const unsigned*)maskp)[tid];   // in-bounds both layouts
        int c = tid & 63, hf = tid >> 6;
        int t_ = timec[b * CTX + c];
        int d_ = distc[b * CTX + c];
        unsigned m_int       = ((const unsigned*)maskp)[b * CTX + c];
        unsigned char m_byte = ((const unsigned char*)maskp)[b * CTX + c];

        int byte_layout = __any_sync(0xFFFFFFFFu, sniffw > 1u);

        int m = byte_layout ? (m_byte != 0) : (m_int != 0);
        float w = m ? 0.5f : 0.0f;
        int idx = hf ? d_ : t_;
        u64 wp = pack2(w);
        #pragma unroll
        for (int s = 0; s < 9; s++)
            sel2[c * 18 + hf * 9 + s] = (idx == s) ? wp : 0ull;
    }
    __syncthreads();   // sel2 visible to all warps

    u64 acc[18];
    #pragma unroll
    for (int s = 0; s < 18; s++) acc[s] = 0ull;

    #pragma unroll
    for (int cc = 0; cc < 8; cc++) {
        int c = g * 8 + cc;
        u64 xc = xv[cc];
        #pragma unroll
        for (int s = 0; s < 18; s++)
            ffma2(acc[s], sel2[c * 18 + s], xc);   // LDS.64 bcast + FFMA2
    }

    #pragma unroll
    for (int s = 0; s < 18; s++)
        *(u64*)&red[g * 2304 + s * 128 + q * 2] = acc[s];
    __syncthreads();

    // fold 8 groups as u64 pairs, coalesced STG.64 into g_Xagg[b][k]
    u64* dstrow = (u64*)(g_Xagg + (size_t)b * KTOT);
    const u64* redp = (const u64*)red;
    for (int i = tid; i < 1152; i += 512) {
        u64 v = redp[i];
        #pragma unroll
        for (int gg = 1; gg < 8; gg++) v = fadd2(v, redp[gg * 1152 + i]);
        dstrow[i] = v;
    }
    if (tid < 128)
        g_Xagg[(size_t)b * KTOT + 2304 + tid] = hv;
}

// ---------------------------------------------------------------------------
// K2: balanced split-K GEMM, 1024 threads (32 warps/SM = 8/SMSP for TLP).
//   grid = (8 n-tiles, 16 K-groups) = 128 blocks (one clean wave).
//   8-way K-split: each thread handles 19 k's x 16 cols for one batch row.
//   dynamic smem: As[152][128] 77824B + Ws[152][16] 9728B = 87552B.
// ---------------------------------------------------------------------------
#define K2_SMEM (152*128*4 + 152*16*4)
__global__ __launch_bounds__(1024, 1)
void k2_gemm(const float* __restrict__ tw,   // [9][128][128]
             const float* __restrict__ dw,   // [9][128][128]
             const float* __restrict__ hw)   // [128][128]
{
    extern __shared__ __align__(16) char smraw2[];
    float* As = (float*)smraw2;                     // [r][b^(r&31)]
    float* Ws = (float*)(smraw2 + 152 * 128 * 4);   // [r][16]

    const int ntile = blockIdx.x;
    const int kg    = blockIdx.y;
    const int tid   = threadIdx.x;
    const int row   = tid & 127;    // batch row
    const int kq    = tid >> 7;     // K eighth (19 k's each)
    const int j0    = ntile * 16;
    const int g0    = kg * KG;      // global k base

    // stage W rows [152][16]: slice resolved per row
    for (int idx = tid; idx < KG * 4; idx += 1024) {
        int r  = idx >> 2;
        int jo = (idx & 3) * 4;
        int kglob = g0 + r;
        int slice = kglob >> 7, krow = kglob & 127;
        const float* Wsrc;
        if (slice < 9)       Wsrc = tw + (size_t)slice * 16384;
        else if (slice < 18) Wsrc = dw + (size_t)(slice - 9) * 16384;
        else                 Wsrc = hw;
        *(float4*)(Ws + r * 16 + jo) =
            *(const float4*)(Wsrc + krow * 128 + j0 + jo);
    }
    // stage A block [152 r][128 b], XOR-swizzled (coalesced LDG, cf STS/LDS)
    {
        #pragma unroll
        for (int i = 0; i < 19; i++) {
            int idx = i * 1024 + tid;         // 0..19455
            int bb = idx / KG;
            int r  = idx - bb * KG;           // consecutive per tid -> coalesced
            As[r * 128 + (bb ^ (r & 31))] =
                g_Xagg[(size_t)bb * KTOT + g0 + r];
        }
    }
    __syncthreads();

    u64 acc[8];
    #pragma unroll
    for (int i = 0; i < 8; i++) acc[i] = 0ull;

    const int rbase = kq * 19;
    #pragma unroll 19
    for (int t = 0; t < 19; t++) {
        int r = rbase + t;
        u64 a2 = pack2(As[r * 128 + (row ^ (r & 31))]);   // LDS.32 cf
        const double2* w = (const double2*)(Ws + r * 16);
        double2 w0 = w[0], w1 = w[1], w2 = w[2], w3 = w[3]; // LDS.128 bcast
        ffma2(acc[0], a2, __double_as_longlong(w0.x));
        ffma2(acc[1], a2, __double_as_longlong(w0.y));
        ffma2(acc[2], a2, __double_as_longlong(w1.x));
        ffma2(acc[3], a2, __double_as_longlong(w1.y));
        ffma2(acc[4], a2, __double_as_longlong(w2.x));
        ffma2(acc[5], a2, __double_as_longlong(w2.y));
        ffma2(acc[6], a2, __double_as_longlong(w3.x));
        ffma2(acc[7], a2, __double_as_longlong(w3.y));
    }

    // combine 8 K-eighths (Cs aliases As after mainloop; 7*128*8 u64 = 56KB)
    __syncthreads();
    u64* Cs = (u64*)As;
    if (kq > 0) {
        u64* cdst = Cs + ((kq - 1) * 128 + row) * 8;
        #pragma unroll
        for (int i = 0; i < 8; i++) cdst[i] = acc[i];
    }
    __syncthreads();
    if (kq == 0) {
        u64* dst = (u64*)(g_gpart + ((size_t)kg * BATCH + row) * HID + j0);
        #pragma unroll
        for (int i = 0; i < 8; i++) {
            u64 v = acc[i];
            #pragma unroll
            for (int p = 0; p < 7; p++)
                v = fadd2(v, Cs[(p * 128 + row) * 8 + i]);
            dst[i] = v;
        }
    }
}

// ---------------------------------------------------------------------------
// K3: fold 16 kgroup partials + sigmoid
// ---------------------------------------------------------------------------
__global__ __launch_bounds__(512)
void k3_sigmoid(float* __restrict__ out)
{
    int i = blockIdx.x * 512 + threadIdx.x;   // 16384 threads
    float v = 0.0f;
    #pragma unroll
    for (int kg = 0; kg < KGROUPS; kg++)
        v += g_gpart[kg * (BATCH * HID) + i];
    out[i] = 1.0f / (1.0f + expf(-v));
}

// ---------------------------------------------------------------------------
extern "C" void kernel_launch(void* const* d_in, const int* in_sizes, int n_in,
                              void* d_out, int out_size)
{
    const float* x    = (const float*)d_in[0];
    const int*   tc   = (const int*)  d_in[1];
    const int*   dc   = (const int*)  d_in[2];
    const void*  mask = (const void*) d_in[3];
    const float* h    = (const float*)d_in[4];
    const float* tw   = (const float*)d_in[5];
    const float* dw   = (const float*)d_in[6];
    const float* hw   = (const float*)d_in[7];
    float* out = (float*)d_out;

    static int attr_done = 0;
    if (!attr_done) {
        cudaFuncSetAttribute(k1_aggregate,
                             cudaFuncAttributeMaxDynamicSharedMemorySize, K1_SMEM);
        cudaFuncSetAttribute(k2_gemm,
                             cudaFuncAttributeMaxDynamicSharedMemorySize, K2_SMEM);
        attr_done = 1;
    }

    k1_aggregate<<<BATCH, 512, K1_SMEM>>>(x, tc, dc, mask, h);
    dim3 g2(8, KGROUPS);
    k2_gemm<<<g2, 1024, K2_SMEM>>>(tw, dw, hw);
    k3_sigmoid<<<BATCH * HID / 512, 512>>>(out);
}

// round 17
// speedup vs baseline: 1.1228x; 1.1228x over previous
#include <cuda_runtime.h>
#include <math.h>

#define BATCH 128
#define CTX 64
#define HID 128
#define KSLICES 19            // 9 time + 9 dist + 1 hidden
#define KTOT (KSLICES*128)    // 2432
#define KGROUPS 16
#define KG 152                // KTOT / KGROUPS

typedef unsigned long long u64;

// Scratch (__device__ globals: allocation-free rule)
__device__ float g_Xagg[BATCH * KTOT];             // [b][k] row-major
__device__ float g_gpart[KGROUPS * BATCH * HID];   // per-kgroup GEMM partials

// ---- packed f32x2 helpers --------------------------------------------------
__device__ __forceinline__ u64 pack2(float v) {
    u64 r; asm("mov.b64 %0, {%1, %1};" : "=l"(r) : "f"(v)); return r;
}
__device__ __forceinline__ void ffma2(u64& d, u64 a, u64 b) {
    asm("fma.rn.f32x2 %0, %1, %2, %0;" : "+l"(d) : "l"(a), "l"(b));
}
__device__ __forceinline__ u64 fadd2(u64 a, u64 b) {
    u64 r; asm("add.rn.f32x2 %0, %1, %2;" : "=l"(r) : "l"(a), "l"(b)); return r;
}

// ---------------------------------------------------------------------------
// K1 (sparse): per-batch slot aggregation via ballot masks.
//   grid = 128 (batch), 608 threads = 19 warps.
//   - stage x[64][128] to smem (one coalesced float4 pass)
//   - tids 0-63: slotT/slotD[c] = slot or 99 if masked (warp-local sniff)
//   - warp w<18 owns (type,slot): 64-bit ballot membership mask, walk set
//     bits ascending (deterministic), sum float4 rows, scale by 0.5 once.
//   - warp 18 copies h into the hidden slice.
//   Work: ~30 issues/warp vs 288/thread in the dense version.
//   static smem: 32KB x + 512B slots.
// ---------------------------------------------------------------------------
__global__ __launch_bounds__(608, 1)
void k1_aggregate(const float* __restrict__ x,     // [B][CTX][128]
                  const int* __restrict__ timec,   // [B][CTX]
                  const int* __restrict__ distc,   // [B][CTX]
                  const void* __restrict__ maskp,  // [B][CTX] int32 OR bytes
                  const float* __restrict__ h)     // [B][128]
{
    __shared__ __align__(16) float xs[CTX * 128];  // 32KB
    __shared__ int slotT[CTX];
    __shared__ int slotD[CTX];

    const int b    = blockIdx.x;
    const int tid  = threadIdx.x;
    const int w    = tid >> 5;
    const int lane = tid & 31;

    // ---- stage x: 2048 float4, coalesced ----
    {
        const float4* src = (const float4*)x + (size_t)b * 2048;
        float4* dst = (float4*)xs;
        for (int i = tid; i < 2048; i += 608)
            dst[i] = src[i];
    }

    // ---- slot arrays (tids 0-63 = warps 0,1; warp-local dtype sniff) ----
    if (tid < 64) {
        int c = tid;
        unsigned sniffw = ((const unsigned*)maskp)[tid];   // in-bounds both layouts
        int byte_layout = __any_sync(0xFFFFFFFFu, sniffw > 1u);
        int t_ = timec[b * CTX + c];
        int d_ = distc[b * CTX + c];
        int m;
        if (byte_layout) m = ((const unsigned char*)maskp)[b * CTX + c] != 0;
        else             m = ((const unsigned*)maskp)[b * CTX + c] != 0;
        slotT[c] = m ? t_ : 99;
        slotD[c] = m ? d_ : 99;
    }
    __syncthreads();

    if (w < 18) {
        const int s = (w < 9) ? w : (w - 9);
        const int* slots = (w < 9) ? slotT : slotD;

        // 64-bit membership mask from two ballots (lanes read c=lane, c=lane+32)
        int sA = slots[lane];
        int sB = slots[lane + 32];
        unsigned mA = __ballot_sync(0xFFFFFFFFu, sA == s);
        unsigned mB = __ballot_sync(0xFFFFFFFFu, sB == s);

        float ax = 0.f, ay = 0.f, az = 0.f, aw = 0.f;
        while (mA) {
            int c = __ffs(mA) - 1;  mA &= mA - 1;
            float4 v = *(const float4*)(xs + c * 128 + lane * 4);
            ax += v.x; ay += v.y; az += v.z; aw += v.w;
        }
        while (mB) {
            int c = (__ffs(mB) - 1) + 32;  mB &= mB - 1;
            float4 v = *(const float4*)(xs + c * 128 + lane * 4);
            ax += v.x; ay += v.y; az += v.z; aw += v.w;
        }
        float4 r = make_float4(0.5f * ax, 0.5f * ay, 0.5f * az, 0.5f * aw);
        *(float4*)(g_Xagg + (size_t)b * KTOT + w * 128 + lane * 4) = r;
    } else {
        // warp 18: hidden slice = h[b][:]
        float4 hv = ((const float4*)(h + (size_t)b * HID))[lane];
        *(float4*)(g_Xagg + (size_t)b * KTOT + 2304 + lane * 4) = hv;
    }
}

// ---------------------------------------------------------------------------
// K2: balanced split-K GEMM (exact R10 best body).
//   grid = (8 n-tiles, 16 K-groups) = 128 blocks (one clean wave).
//   512 threads = 4 K-quarters x 128 rows; 152 k's x 16 cols per block.
//   dynamic smem: As[152][128] 77824B + Ws[152][16] 9728B = 87552B.
// ---------------------------------------------------------------------------
#define K2_SMEM (152*128*4 + 152*16*4)
__global__ __launch_bounds__(512, 1)
void k2_gemm(const float* __restrict__ tw,   // [9][128][128]
             const float* __restrict__ dw,   // [9][128][128]
             const float* __restrict__ hw)   // [128][128]
{
    extern __shared__ __align__(16) char smraw2[];
    float* As = (float*)smraw2;                     // [r][b^(r&31)]
    float* Ws = (float*)(smraw2 + 152 * 128 * 4);   // [r][16]

    const int ntile = blockIdx.x;
    const int kg    = blockIdx.y;
    const int tid   = threadIdx.x;
    const int row   = tid & 127;    // batch row
    const int kq    = tid >> 7;     // K quarter (38 k's each)
    const int j0    = ntile * 16;
    const int g0    = kg * KG;      // global k base

    // stage W rows [152][16]: slice resolved per row
    for (int idx = tid; idx < KG * 4; idx += 512) {
        int r  = idx >> 2;
        int jo = (idx & 3) * 4;
        int kglob = g0 + r;
        int slice = kglob >> 7, krow = kglob & 127;
        const float* Wsrc;
        if (slice < 9)       Wsrc = tw + (size_t)slice * 16384;
        else if (slice < 18) Wsrc = dw + (size_t)(slice - 9) * 16384;
        else                 Wsrc = hw;
        *(float4*)(Ws + r * 16 + jo) =
            *(const float4*)(Wsrc + krow * 128 + j0 + jo);
    }
    // stage A block [152 r][128 b], XOR-swizzled (coalesced LDG, cf STS/LDS)
    {
        #pragma unroll
        for (int i = 0; i < 38; i++) {
            int idx = i * 512 + tid;          // 0..19455
            int bb = idx / KG;
            int r  = idx - bb * KG;           // consecutive per tid -> coalesced
            As[r * 128 + (bb ^ (r & 31))] =
                g_Xagg[(size_t)bb * KTOT + g0 + r];
        }
    }
    __syncthreads();

    u64 acc[8];
    #pragma unroll
    for (int i = 0; i < 8; i++) acc[i] = 0ull;

    const int rbase = kq * 38;
    #pragma unroll 19
    for (int t = 0; t < 38; t++) {
        int r = rbase + t;
        u64 a2 = pack2(As[r * 128 + (row ^ (r & 31))]);   // LDS.32 cf
        const double2* w = (const double2*)(Ws + r * 16);
        double2 w0 = w[0], w1 = w[1], w2 = w[2], w3 = w[3]; // LDS.128 bcast
        ffma2(acc[0], a2, __double_as_longlong(w0.x));
        ffma2(acc[1], a2, __double_as_longlong(w0.y));
        ffma2(acc[2], a2, __double_as_longlong(w1.x));
        ffma2(acc[3], a2, __double_as_longlong(w1.y));
        ffma2(acc[4], a2, __double_as_longlong(w2.x));
        ffma2(acc[5], a2, __double_as_longlong(w2.y));
        ffma2(acc[6], a2, __double_as_longlong(w3.x));
        ffma2(acc[7], a2, __double_as_longlong(w3.y));
    }

    // combine 4 K-quarters (Cs aliases As after mainloop)
    __syncthreads();
    u64* Cs = (u64*)As;
    if (kq > 0) {
        u64* cdst = Cs + ((kq - 1) * 128 + row) * 8;
        #pragma unroll
        for (int i = 0; i < 8; i++) cdst[i] = acc[i];
    }
    __syncthreads();
    if (kq == 0) {
        u64* dst = (u64*)(g_gpart + ((size_t)kg * BATCH + row) * HID + j0);
        #pragma unroll
        for (int i = 0; i < 8; i++) {
            u64 v = acc[i];
            v = fadd2(v, Cs[(0 * 128 + row) * 8 + i]);
            v = fadd2(v, Cs[(1 * 128 + row) * 8 + i]);
            v = fadd2(v, Cs[(2 * 128 + row) * 8 + i]);
            dst[i] = v;
        }
    }
}

// ---------------------------------------------------------------------------
// K3: fold 16 kgroup partials + sigmoid
// ---------------------------------------------------------------------------
__global__ __launch_bounds__(512)
void k3_sigmoid(float* __restrict__ out)
{
    int i = blockIdx.x * 512 + threadIdx.x;   // 16384 threads
    float v = 0.0f;
    #pragma unroll
    for (int kg = 0; kg < KGROUPS; kg++)
        v += g_gpart[kg * (BATCH * HID) + i];
    out[i] = 1.0f / (1.0f + expf(-v));
}

// ---------------------------------------------------------------------------
extern "C" void kernel_launch(void* const* d_in, const int* in_sizes, int n_in,
                              void* d_out, int out_size)
{
    const float* x    = (const float*)d_in[0];
    const int*   tc   = (const int*)  d_in[1];
    const int*   dc   = (const int*)  d_in[2];
    const void*  mask = (const void*) d_in[3];
    const float* h    = (const float*)d_in[4];
    const float* tw   = (const float*)d_in[5];
    const float* dw   = (const float*)d_in[6];
    const float* hw   = (const float*)d_in[7];
    float* out = (float*)d_out;

    static int attr_done = 0;
    if (!attr_done) {
        cudaFuncSetAttribute(k2_gemm,
                             cudaFuncAttributeMaxDynamicSharedMemorySize, K2_SMEM);
        attr_done = 1;
    }

    k1_aggregate<<<BATCH, 608>>>(x, tc, dc, mask, h);
    dim3 g2(8, KGROUPS);
    k2_gemm<<<g2, 512, K2_SMEM>>>(tw, dw, hw);
    k3_sigmoid<<<BATCH * HID / 512, 512>>>(out);
}